// round 4
// baseline (speedup 1.0000x reference)
#include <cuda_runtime.h>
#include <cuda_bf16.h>
#include <cstdint>

#define B_   64
#define T_   2048
#define DIN  128
#define H_   512
#define DOUT 128

#define KC   64      // K elems per chunk (128B bf16 rows)
#define TPB  256

// ---- arch feature gate: tcgen05 only in the sm_103a/sm_100a pass ----
#if defined(__CUDA_ARCH__) && (defined(__CUDA_ARCH_FEAT_SM103_ALL) || defined(__CUDA_ARCH_FEAT_SM100_ALL))
#define USE_TC 1
#else
#define USE_TC 0
#endif

// idesc kind::f16: dtype=F32(1<<4) atype=BF16(1<<7) btype=BF16(1<<10) N=256(32<<17) M=128(8<<24)
#define IDESC_128x256 0x8400490u

// SMEM: [0:4) tmem ptr; mbars at 64; two 96KB chunk buffers at 1024
#define MB_BUFFREE0  64
#define MB_BUFFREE1  72
#define MB_TILERDY0  80
#define MB_TILERDY1  88
#define MB_SCAND0    96
#define MB_SCAND1    104
#define CHUNK_BYTES  98304            // WH 16K | WL 16K | XH 32K | XL 32K
#define OFF_WH 0
#define OFF_WL 16384
#define OFF_XH 32768
#define OFF_XL 65536
#define SM_BUF0 1024
#define SM_TOTAL (1024 + 2*CHUNK_BYTES)

// ---------------- scratch ----------------
__device__ uint32_t g_h1[(size_t)B_ * T_ * H_];   // packed bf16 hi|lo
__device__ uint32_t g_h2[(size_t)B_ * T_ * H_];
__device__ __nv_bfloat16 g_W0hi[H_ * DIN];
__device__ __nv_bfloat16 g_W0lo[H_ * DIN];
__device__ __nv_bfloat16 g_W1hi[H_ * H_];
__device__ __nv_bfloat16 g_W1lo[H_ * H_];
__device__ __nv_bfloat16 g_fWhi[DOUT * H_];
__device__ __nv_bfloat16 g_fWlo[DOUT * H_];

__device__ __forceinline__ uint32_t bfpack2(float a, float b) {
    return (uint32_t)__bfloat16_as_ushort(__float2bfloat16(a))
         | ((uint32_t)__bfloat16_as_ushort(__float2bfloat16(b)) << 16);
}
__device__ __forceinline__ uint32_t packhl(float v) {
    __nv_bfloat16 h = __float2bfloat16(v);
    __nv_bfloat16 l = __float2bfloat16(v - __bfloat162float(h));
    return (uint32_t)__bfloat16_as_ushort(h) | ((uint32_t)__bfloat16_as_ushort(l) << 16);
}
__device__ __forceinline__ float unpackhl(uint32_t p) {
    return __bfloat162float(__ushort_as_bfloat16((unsigned short)(p & 0xFFFF)))
         + __bfloat162float(__ushort_as_bfloat16((unsigned short)(p >> 16)));
}

#if USE_TC
// ---------------- PTX helpers ----------------
__device__ __forceinline__ uint32_t smem_to_u32(const void* p) {
    uint32_t a;
    asm("{ .reg .u64 t; cvta.to.shared.u64 t, %1; cvt.u32.u64 %0, t; }" : "=r"(a) : "l"(p));
    return a;
}
__device__ __forceinline__ uint32_t elect_one_pred() {
    uint32_t p;
    asm volatile("{\n\t.reg .pred p;\n\telect.sync _|p, 0xFFFFFFFF;\n\tselp.b32 %0, 1, 0, p;\n\t}" : "=r"(p));
    return p;
}
#define MBAR_INIT(a, c) asm volatile("mbarrier.init.shared.b64 [%0], %1;" :: "r"(a), "r"(c) : "memory")
#define MBAR_INVAL(a)   asm volatile("mbarrier.inval.shared.b64 [%0];" :: "r"(a) : "memory")
#define MBAR_ARRIVE(a)  asm volatile("mbarrier.arrive.shared.b64 _, [%0];" :: "r"(a) : "memory")
#define MBAR_WAIT(a, ph) do {                                                       \
    uint32_t _m = (a), _p = (ph), _d;                                               \
    asm volatile("{\n\t.reg .pred p;\n\t"                                           \
        "mbarrier.try_wait.parity.acquire.cta.shared::cta.b64 p, [%1], %2;\n\t"     \
        "selp.b32 %0, 1, 0, p;\n\t}" : "=r"(_d) : "r"(_m), "r"(_p) : "memory");     \
    if (!_d) {                                                                      \
        asm volatile("{\n\t.reg .pred P1;\n\tWL_%=:\n\t"                            \
            "mbarrier.try_wait.parity.acquire.cta.shared::cta.b64 P1, [%0], %1, 0x989680;\n\t" \
            "@P1 bra.uni WD_%=;\n\tbra.uni WL_%=;\n\tWD_%=:\n\t}"                   \
            :: "r"(_m), "r"(_p) : "memory");                                        \
    }                                                                               \
} while (0)
#define TC_ALLOC(sa, n)   asm volatile("tcgen05.alloc.cta_group::1.sync.aligned.shared::cta.b32 [%0], %1;" :: "r"(sa), "r"(n) : "memory")
#define TC_DEALLOC(t, n)  asm volatile("tcgen05.dealloc.cta_group::1.sync.aligned.b32 %0, %1;" :: "r"(t), "r"(n))
#define TC_RELINQ()       asm volatile("tcgen05.relinquish_alloc_permit.cta_group::1.sync.aligned;")
#define TC_COMMIT(mb)     asm volatile("tcgen05.commit.cta_group::1.mbarrier::arrive::one.shared::cluster.b64 [%0];" :: "r"(mb) : "memory")
#define TC_WAIT_LD()      asm volatile("tcgen05.wait::ld.sync.aligned;" ::: "memory")
#define TC_FENCE_BEFORE() asm volatile("tcgen05.fence::before_thread_sync;" ::: "memory")
#define TC_FENCE_AFTER()  asm volatile("tcgen05.fence::after_thread_sync;" ::: "memory")
#define FENCE_ASYNC()     asm volatile("fence.proxy.async.shared::cta;" ::: "memory")
#define BAR_PROD()        asm volatile("bar.sync 1, 128;" ::: "memory")

__device__ __forceinline__ void mma_f16_ss(uint32_t d, uint64_t ad, uint64_t bd,
                                           uint32_t idesc, uint32_t en) {
    asm volatile(
        "{\n\t.reg .pred p;\n\tsetp.ne.u32 p, %5, 0;\n\t"
        "tcgen05.mma.cta_group::1.kind::f16 [%0], %1, %2, %3, {%4, %4, %4, %4}, p;\n\t}"
        :: "r"(d), "l"(ad), "l"(bd), "r"(idesc), "r"(0u), "r"(en) : "memory");
}
__device__ __forceinline__ uint64_t mk_desc(uint32_t addr) {
    return ((uint64_t)2 << 61) | ((uint64_t)1 << 46) | ((uint64_t)64 << 32)
         | ((uint64_t)1 << 16) | ((uint64_t)(addr >> 4) & 0x3FFF);
}
#define LDTM_X32(r, a)                                                              \
    asm volatile("tcgen05.ld.sync.aligned.32x32b.x32.b32 "                          \
        "{%0,%1,%2,%3,%4,%5,%6,%7,%8,%9,%10,%11,%12,%13,%14,%15,"                   \
        "%16,%17,%18,%19,%20,%21,%22,%23,%24,%25,%26,%27,%28,%29,%30,%31}, [%32];"  \
        : "=r"((r)[0]),"=r"((r)[1]),"=r"((r)[2]),"=r"((r)[3]),                       \
          "=r"((r)[4]),"=r"((r)[5]),"=r"((r)[6]),"=r"((r)[7]),                       \
          "=r"((r)[8]),"=r"((r)[9]),"=r"((r)[10]),"=r"((r)[11]),                     \
          "=r"((r)[12]),"=r"((r)[13]),"=r"((r)[14]),"=r"((r)[15]),                   \
          "=r"((r)[16]),"=r"((r)[17]),"=r"((r)[18]),"=r"((r)[19]),                   \
          "=r"((r)[20]),"=r"((r)[21]),"=r"((r)[22]),"=r"((r)[23]),                   \
          "=r"((r)[24]),"=r"((r)[25]),"=r"((r)[26]),"=r"((r)[27]),                   \
          "=r"((r)[28]),"=r"((r)[29]),"=r"((r)[30]),"=r"((r)[31]) : "r"(a))

// chunk loader: 128 producer threads fill WH/WL (128x64 bf16) + XH/XL (256x64 bf16), SW128.
template <int K, int XPACKED>
__device__ __forceinline__ void load_chunk(char* buf, const char* Xv,
                                           const __nv_bfloat16* Whi, const __nv_bfloat16* Wlo,
                                           int h0, int bp, int t0, int kc, int ltid) {
    // X: rows 0..127 = batch bp*2 (t0+ltid), rows 128..255 = batch bp*2+1
    #pragma unroll
    for (int q = 0; q < 2; q++) {
        const int bmat = bp * 2 + q;
        const int r = q * 128 + ltid;
        const size_t rowelem = ((size_t)bmat * T_ + (t0 + ltid)) * K + kc;
        #pragma unroll
        for (int p = 0; p < 8; p++) {
            uint4 hi, lo;
            if (XPACKED) {
                const uint4* xr = (const uint4*)((const uint32_t*)Xv + rowelem);
                uint4 v0 = __ldg(&xr[2 * p]);
                uint4 v1 = __ldg(&xr[2 * p + 1]);
                hi.x = __byte_perm(v0.x, v0.y, 0x5410); hi.y = __byte_perm(v0.z, v0.w, 0x5410);
                hi.z = __byte_perm(v1.x, v1.y, 0x5410); hi.w = __byte_perm(v1.z, v1.w, 0x5410);
                lo.x = __byte_perm(v0.x, v0.y, 0x7632); lo.y = __byte_perm(v0.z, v0.w, 0x7632);
                lo.z = __byte_perm(v1.x, v1.y, 0x7632); lo.w = __byte_perm(v1.z, v1.w, 0x7632);
            } else {
                const float4* xr = (const float4*)((const float*)Xv + rowelem);
                float4 v0 = __ldg(&xr[2 * p]);
                float4 v1 = __ldg(&xr[2 * p + 1]);
                float f[8] = {v0.x, v0.y, v0.z, v0.w, v1.x, v1.y, v1.z, v1.w};
                float l[8];
                #pragma unroll
                for (int e = 0; e < 8; e++)
                    l[e] = f[e] - __bfloat162float(__float2bfloat16(f[e]));
                hi.x = bfpack2(f[0], f[1]); hi.y = bfpack2(f[2], f[3]);
                hi.z = bfpack2(f[4], f[5]); hi.w = bfpack2(f[6], f[7]);
                lo.x = bfpack2(l[0], l[1]); lo.y = bfpack2(l[2], l[3]);
                lo.z = bfpack2(l[4], l[5]); lo.w = bfpack2(l[6], l[7]);
            }
            uint32_t off = r * 128 + p * 16;
            uint32_t sw = off ^ ((off >> 3) & 0x70);
            *(uint4*)(buf + OFF_XH + sw) = hi;
            *(uint4*)(buf + OFF_XL + sw) = lo;
        }
    }
    // W: row ltid
    {
        const int r = ltid;
        const uint4* wh = (const uint4*)(Whi + (size_t)(h0 + r) * K + kc);
        const uint4* wl = (const uint4*)(Wlo + (size_t)(h0 + r) * K + kc);
        #pragma unroll
        for (int i = 0; i < 8; i++) {
            uint32_t off = r * 128 + i * 16;
            uint32_t sw = off ^ ((off >> 3) & 0x70);
            *(uint4*)(buf + OFF_WH + sw) = __ldg(&wh[i]);
            *(uint4*)(buf + OFF_WL + sw) = __ldg(&wl[i]);
        }
    }
}
#endif  // USE_TC

// ---------------- weight split ----------------
__global__ void split_kernel(const float* __restrict__ src,
                             __nv_bfloat16* __restrict__ hi,
                             __nv_bfloat16* __restrict__ lo, int n) {
    for (int i = blockIdx.x * blockDim.x + threadIdx.x; i < n; i += gridDim.x * blockDim.x) {
        float v = src[i];
        __nv_bfloat16 h = __float2bfloat16(v);
        hi[i] = h;
        lo[i] = __float2bfloat16(v - __bfloat162float(h));
    }
}

// ================ fused layer: GEMM (bf16x2) + in-register scan ================
// grid (4 hblocks, 32 bpairs), block 256. D[128 h-lanes, 256 cols = 2b x 128t].
// warps 0-3: scan consumer; warps 4-7: load producer + MMA issue (warp 4 elect).
template <int K, int XPACKED>
__global__ void __launch_bounds__(TPB, 1)
layer_tc(const char* __restrict__ Xv,
         const __nv_bfloat16* __restrict__ Whi, const __nv_bfloat16* __restrict__ Wlo,
         const float* __restrict__ bl, const float* __restrict__ u, const float* __restrict__ bb,
         uint32_t* __restrict__ Hp) {
    extern __shared__ char smem[];
    const int tid = threadIdx.x;
    const int h0 = blockIdx.x * 128;
    const int bp = blockIdx.y;
#if USE_TC
    constexpr int C = K / KC;
    constexpr int NTILES = T_ / 128;
    const uint32_t smb = smem_to_u32(smem);
    const int wid = tid >> 5;

    if (tid == 0) {
        MBAR_INIT(smb + MB_BUFFREE0, 1); MBAR_INIT(smb + MB_BUFFREE1, 1);
        MBAR_INIT(smb + MB_TILERDY0, 1); MBAR_INIT(smb + MB_TILERDY1, 1);
        MBAR_INIT(smb + MB_SCAND0, 128); MBAR_INIT(smb + MB_SCAND1, 128);
    }
    if (wid == 0) { TC_ALLOC(smb, 512); TC_RELINQ(); }
    __syncthreads();
    uint32_t tmem;
    asm volatile("ld.shared.b32 %0, [%1];" : "=r"(tmem) : "r"(smb));

    if (wid >= 4) {
        // ---------------- producer ----------------
        const int ltid = tid - 128;
        int cnt[2] = {0, 0};
        for (int j = 0; j < NTILES; j++) {
            const int t0 = j * 128;
            for (int c = 0; c < C; c++) {
                const int b = (j * C + c) & 1;
                if (cnt[b]) MBAR_WAIT(smb + MB_BUFFREE0 + 8 * b, (cnt[b] - 1) & 1);
                char* buf = smem + SM_BUF0 + b * CHUNK_BYTES;
                load_chunk<K, XPACKED>(buf, Xv, Whi, Wlo, h0, bp, t0, c * KC, ltid);
                BAR_PROD();
                FENCE_ASYNC();
                if (wid == 4 && elect_one_pred()) {
                    if (c == 0 && j >= 2)
                        MBAR_WAIT(smb + MB_SCAND0 + 8 * (j & 1), ((j >> 1) - 1) & 1);
                    const uint32_t smbuf = smb + SM_BUF0 + b * CHUNK_BYTES;
                    const uint64_t dWH = mk_desc(smbuf + OFF_WH), dWL = mk_desc(smbuf + OFF_WL);
                    const uint64_t dXH = mk_desc(smbuf + OFF_XH), dXL = mk_desc(smbuf + OFF_XL);
                    const uint32_t dacc = tmem + (j & 1) * 256;
                    #pragma unroll
                    for (int k = 0; k < 4; k++) {
                        const uint64_t o = (uint64_t)(k * 2);
                        mma_f16_ss(dacc, dWH + o, dXH + o, IDESC_128x256,
                                   (c == 0 && k == 0) ? 0u : 1u);
                        mma_f16_ss(dacc, dWH + o, dXL + o, IDESC_128x256, 1u);
                        mma_f16_ss(dacc, dWL + o, dXH + o, IDESC_128x256, 1u);
                    }
                    TC_COMMIT(smb + MB_BUFFREE0 + 8 * b);
                    if (c == C - 1) TC_COMMIT(smb + MB_TILERDY0 + 8 * (j & 1));
                }
                cnt[b]++;
            }
        }
    } else {
        // ---------------- consumer: per-channel scan ----------------
        float car[2] = {0.0f, 0.0f};
        const float uu = u[h0 + tid];
        const float bi = bl[h0 + tid] + bb[h0 + tid];
        for (int j = 0; j < NTILES; j++) {
            const int t0 = j * 128;
            MBAR_WAIT(smb + MB_TILERDY0 + 8 * (j & 1), (j >> 1) & 1);
            TC_FENCE_AFTER();
            const uint32_t dbase = tmem + (j & 1) * 256;
            #pragma unroll
            for (int cb = 0; cb < 8; cb++) {
                uint32_t d[32];
                LDTM_X32(d, dbase + cb * 32);
                TC_WAIT_LD();
                const int q = cb >> 2;
                const int tb = (cb & 3) * 32;
                uint32_t* hp = Hp + ((size_t)(bp * 2 + q) * T_ + t0 + tb) * H_ + h0 + tid;
                float cr = car[q];
                #pragma unroll
                for (int i = 0; i < 32; i++) {
                    float p = __uint_as_float(d[i]) + bi;
                    cr = fmaxf(fmaf(uu, cr, p), 0.0f);
                    hp[(size_t)i * H_] = packhl(cr);
                }
                car[q] = cr;
            }
            TC_FENCE_BEFORE();
            MBAR_ARRIVE(smb + MB_SCAND0 + 8 * (j & 1));
        }
    }
    __syncthreads();
    if (tid == 0) {
        MBAR_INVAL(smb + MB_BUFFREE0); MBAR_INVAL(smb + MB_BUFFREE1);
        MBAR_INVAL(smb + MB_TILERDY0); MBAR_INVAL(smb + MB_TILERDY1);
        MBAR_INVAL(smb + MB_SCAND0);   MBAR_INVAL(smb + MB_SCAND1);
    }
    __syncthreads();
    if (wid == 0) TC_DEALLOC(tmem, 512);
#else
    // SIMT fallback
    float* xrow = (float*)smem;
    const int h = h0 + (tid < 128 ? tid : 0);
    float uu = 0.0f, bi = 0.0f;
    if (tid < 128) { uu = u[h]; bi = bl[h] + bb[h]; }
    const __nv_bfloat16* wh = Whi + (size_t)h * K;
    const __nv_bfloat16* wl = Wlo + (size_t)h * K;
    for (int q = 0; q < 2; q++) {
        const int bmat = bp * 2 + q;
        float hcar = 0.0f;
        for (int t = 0; t < T_; t++) {
            __syncthreads();
            size_t xr = ((size_t)bmat * T_ + t) * K;
            for (int i = tid; i < K; i += TPB)
                xrow[i] = XPACKED ? unpackhl(((const uint32_t*)Xv)[xr + i])
                                  : ((const float*)Xv)[xr + i];
            __syncthreads();
            if (tid < 128) {
                float acc = 0.0f;
                for (int k = 0; k < K; k++)
                    acc += (__bfloat162float(wh[k]) + __bfloat162float(wl[k])) * xrow[k];
                hcar = fmaxf(acc + bi + uu * hcar, 0.0f);
                Hp[((size_t)bmat * T_ + t) * H_ + h0 + tid] = packhl(hcar);
            }
        }
    }
#endif
}

// ================ FC: out[b,t,o] = h2 . fcW[o,:] + fcb[o] ================
// grid (4 tgroups, 32 bpairs), block 256.
__global__ void __launch_bounds__(TPB, 1)
fc_tc(const char* __restrict__ Xv,
      const __nv_bfloat16* __restrict__ Whi, const __nv_bfloat16* __restrict__ Wlo,
      const float* __restrict__ bias, float* __restrict__ out) {
    extern __shared__ char smem[];
    const int tid = threadIdx.x;
    const int tg = blockIdx.x;
    const int bp = blockIdx.y;
#if USE_TC
    constexpr int C = H_ / KC;   // 8
    constexpr int NTILES = 4;
    const uint32_t smb = smem_to_u32(smem);
    const int wid = tid >> 5;

    if (tid == 0) {
        MBAR_INIT(smb + MB_BUFFREE0, 1); MBAR_INIT(smb + MB_BUFFREE1, 1);
        MBAR_INIT(smb + MB_TILERDY0, 1); MBAR_INIT(smb + MB_TILERDY1, 1);
        MBAR_INIT(smb + MB_SCAND0, 128); MBAR_INIT(smb + MB_SCAND1, 128);
    }
    if (wid == 0) { TC_ALLOC(smb, 512); TC_RELINQ(); }
    __syncthreads();
    uint32_t tmem;
    asm volatile("ld.shared.b32 %0, [%1];" : "=r"(tmem) : "r"(smb));

    if (wid >= 4) {
        const int ltid = tid - 128;
        int cnt[2] = {0, 0};
        for (int j = 0; j < NTILES; j++) {
            const int t0 = tg * 512 + j * 128;
            for (int c = 0; c < C; c++) {
                const int b = (j * C + c) & 1;
                if (cnt[b]) MBAR_WAIT(smb + MB_BUFFREE0 + 8 * b, (cnt[b] - 1) & 1);
                char* buf = smem + SM_BUF0 + b * CHUNK_BYTES;
                load_chunk<H_, 1>(buf, Xv, Whi, Wlo, 0, bp, t0, c * KC, ltid);
                BAR_PROD();
                FENCE_ASYNC();
                if (wid == 4 && elect_one_pred()) {
                    if (c == 0 && j >= 2)
                        MBAR_WAIT(smb + MB_SCAND0 + 8 * (j & 1), ((j >> 1) - 1) & 1);
                    const uint32_t smbuf = smb + SM_BUF0 + b * CHUNK_BYTES;
                    const uint64_t dWH = mk_desc(smbuf + OFF_WH), dWL = mk_desc(smbuf + OFF_WL);
                    const uint64_t dXH = mk_desc(smbuf + OFF_XH), dXL = mk_desc(smbuf + OFF_XL);
                    const uint32_t dacc = tmem + (j & 1) * 256;
                    #pragma unroll
                    for (int k = 0; k < 4; k++) {
                        const uint64_t o = (uint64_t)(k * 2);
                        mma_f16_ss(dacc, dWH + o, dXH + o, IDESC_128x256,
                                   (c == 0 && k == 0) ? 0u : 1u);
                        mma_f16_ss(dacc, dWH + o, dXL + o, IDESC_128x256, 1u);
                        mma_f16_ss(dacc, dWL + o, dXH + o, IDESC_128x256, 1u);
                    }
                    TC_COMMIT(smb + MB_BUFFREE0 + 8 * b);
                    if (c == C - 1) TC_COMMIT(smb + MB_TILERDY0 + 8 * (j & 1));
                }
                cnt[b]++;
            }
        }
    } else {
        const float bo = bias[tid];
        for (int j = 0; j < NTILES; j++) {
            const int t0 = tg * 512 + j * 128;
            MBAR_WAIT(smb + MB_TILERDY0 + 8 * (j & 1), (j >> 1) & 1);
            TC_FENCE_AFTER();
            const uint32_t dbase = tmem + (j & 1) * 256;
            #pragma unroll
            for (int cb = 0; cb < 8; cb++) {
                uint32_t d[32];
                LDTM_X32(d, dbase + cb * 32);
                TC_WAIT_LD();
                const int q = cb >> 2;
                const int tb = (cb & 3) * 32;
                float* op = out + ((size_t)(bp * 2 + q) * T_ + t0 + tb) * DOUT + tid;
                #pragma unroll
                for (int i = 0; i < 32; i++)
                    op[(size_t)i * DOUT] = __uint_as_float(d[i]) + bo;
            }
            TC_FENCE_BEFORE();
            MBAR_ARRIVE(smb + MB_SCAND0 + 8 * (j & 1));
        }
    }
    __syncthreads();
    if (tid == 0) {
        MBAR_INVAL(smb + MB_BUFFREE0); MBAR_INVAL(smb + MB_BUFFREE1);
        MBAR_INVAL(smb + MB_TILERDY0); MBAR_INVAL(smb + MB_TILERDY1);
        MBAR_INVAL(smb + MB_SCAND0);   MBAR_INVAL(smb + MB_SCAND1);
    }
    __syncthreads();
    if (wid == 0) TC_DEALLOC(tmem, 512);
#else
    // SIMT fallback
    float* xrow = (float*)smem;
    const __nv_bfloat16* wh = Whi + (size_t)(tid < 128 ? tid : 0) * H_;
    const __nv_bfloat16* wl = Wlo + (size_t)(tid < 128 ? tid : 0) * H_;
    float bo = (tid < 128) ? bias[tid] : 0.0f;
    for (int q = 0; q < 2; q++) {
        const int bmat = bp * 2 + q;
        for (int tt = 0; tt < 512; tt++) {
            const int t = tg * 512 + tt;
            __syncthreads();
            size_t xr = ((size_t)bmat * T_ + t) * H_;
            for (int i = tid; i < H_; i += TPB)
                xrow[i] = unpackhl(((const uint32_t*)Xv)[xr + i]);
            __syncthreads();
            if (tid < 128) {
                float acc = 0.0f;
                for (int k = 0; k < H_; k++)
                    acc += (__bfloat162float(wh[k]) + __bfloat162float(wl[k])) * xrow[k];
                out[((size_t)bmat * T_ + t) * DOUT + tid] = acc + bo;
            }
        }
    }
#endif
}

extern "C" void kernel_launch(void* const* d_in, const int* in_sizes, int n_in,
                              void* d_out, int out_size) {
    const float* x   = (const float*)d_in[0];
    const float* W0  = (const float*)d_in[1];
    const float* bl0 = (const float*)d_in[2];
    const float* u0  = (const float*)d_in[3];
    const float* bb0 = (const float*)d_in[4];
    const float* W1  = (const float*)d_in[5];
    const float* bl1 = (const float*)d_in[6];
    const float* u1  = (const float*)d_in[7];
    const float* bb1 = (const float*)d_in[8];
    const float* fcW = (const float*)d_in[9];
    const float* fcb = (const float*)d_in[10];
    float* out = (float*)d_out;

    uint32_t *h1p, *h2p;
    __nv_bfloat16 *w0hi, *w0lo, *w1hi, *w1lo, *fwhi, *fwlo;
    cudaGetSymbolAddress((void**)&h1p,  g_h1);
    cudaGetSymbolAddress((void**)&h2p,  g_h2);
    cudaGetSymbolAddress((void**)&w0hi, g_W0hi);
    cudaGetSymbolAddress((void**)&w0lo, g_W0lo);
    cudaGetSymbolAddress((void**)&w1hi, g_W1hi);
    cudaGetSymbolAddress((void**)&w1lo, g_W1lo);
    cudaGetSymbolAddress((void**)&fwhi, g_fWhi);
    cudaGetSymbolAddress((void**)&fwlo, g_fWlo);

    cudaFuncSetAttribute(layer_tc<DIN, 0>, cudaFuncAttributeMaxDynamicSharedMemorySize, SM_TOTAL);
    cudaFuncSetAttribute(layer_tc<H_, 1>,  cudaFuncAttributeMaxDynamicSharedMemorySize, SM_TOTAL);
    cudaFuncSetAttribute(fc_tc,            cudaFuncAttributeMaxDynamicSharedMemorySize, SM_TOTAL);

    split_kernel<<<64,  256>>>(W0,  w0hi, w0lo, H_ * DIN);
    split_kernel<<<256, 256>>>(W1,  w1hi, w1lo, H_ * H_);
    split_kernel<<<64,  256>>>(fcW, fwhi, fwlo, DOUT * H_);

    dim3 lgrid(H_ / 128, B_ / 2);     // (4, 32)
    layer_tc<DIN, 0><<<lgrid, TPB, SM_TOTAL>>>((const char*)x, w0hi, w0lo, bl0, u0, bb0, h1p);
    layer_tc<H_, 1> <<<lgrid, TPB, SM_TOTAL>>>((const char*)h1p, w1hi, w1lo, bl1, u1, bb1, h2p);
    dim3 fgrid(4, B_ / 2);            // (4, 32)
    fc_tc<<<fgrid, TPB, SM_TOTAL>>>((const char*)h2p, fwhi, fwlo, fcb, out);
}

// round 7
// speedup vs baseline: 1.1048x; 1.1048x over previous
#include <cuda_runtime.h>
#include <cuda_bf16.h>
#include <cstdint>

#define B_   64
#define T_   2048
#define DIN  128
#define H_   512
#define DOUT 128

#define KC   64      // K elems per chunk (128B bf16 rows)
#define TPB  256

#if defined(__CUDA_ARCH__) && (defined(__CUDA_ARCH_FEAT_SM103_ALL) || defined(__CUDA_ARCH_FEAT_SM100_ALL))
#define USE_TC 1
#else
#define USE_TC 0
#endif

// idesc kind::f16: dtype=F32(1<<4) atype=BF16(1<<7) btype=BF16(1<<10) N=256(32<<17) M=128(8<<24)
#define IDESC_128x256 0x8400490u

// SMEM: [0:4) tmem ptr; mbars at 64; two 96KB chunk buffers at 1024
#define MB_BUFFREE0  64
#define MB_TILERDY0  80
#define MB_SCAND0    96
#define CHUNK_BYTES  98304            // WH 16K | WL 16K | XH 32K | XL 32K
#define OFF_WH 0
#define OFF_WL 16384
#define OFF_XH 32768
#define OFF_XL 65536
#define SM_BUF0 1024
#define SM_TOTAL (1024 + 2*CHUNK_BYTES)

// ---------------- scratch: planar bf16 hi/lo ----------------
__device__ __nv_bfloat16 g_xhi[(size_t)B_ * T_ * DIN];
__device__ __nv_bfloat16 g_xlo[(size_t)B_ * T_ * DIN];
__device__ __nv_bfloat16 g_h1hi[(size_t)B_ * T_ * H_];
__device__ __nv_bfloat16 g_h1lo[(size_t)B_ * T_ * H_];
__device__ __nv_bfloat16 g_h2hi[(size_t)B_ * T_ * H_];
__device__ __nv_bfloat16 g_h2lo[(size_t)B_ * T_ * H_];
__device__ __nv_bfloat16 g_W0hi[H_ * DIN];
__device__ __nv_bfloat16 g_W0lo[H_ * DIN];
__device__ __nv_bfloat16 g_W1hi[H_ * H_];
__device__ __nv_bfloat16 g_W1lo[H_ * H_];
__device__ __nv_bfloat16 g_fWhi[DOUT * H_];
__device__ __nv_bfloat16 g_fWlo[DOUT * H_];

#if USE_TC
// ---------------- PTX helpers ----------------
__device__ __forceinline__ uint32_t smem_to_u32(const void* p) {
    uint32_t a;
    asm("{ .reg .u64 t; cvta.to.shared.u64 t, %1; cvt.u32.u64 %0, t; }" : "=r"(a) : "l"(p));
    return a;
}
__device__ __forceinline__ uint32_t elect_one_pred() {
    uint32_t p;
    asm volatile("{\n\t.reg .pred p;\n\telect.sync _|p, 0xFFFFFFFF;\n\tselp.b32 %0, 1, 0, p;\n\t}" : "=r"(p));
    return p;
}
#define MBAR_INIT(a, c) asm volatile("mbarrier.init.shared.b64 [%0], %1;" :: "r"(a), "r"(c) : "memory")
#define MBAR_INVAL(a)   asm volatile("mbarrier.inval.shared.b64 [%0];" :: "r"(a) : "memory")
#define MBAR_ARRIVE(a)  asm volatile("mbarrier.arrive.shared.b64 _, [%0];" :: "r"(a) : "memory")
#define MBAR_WAIT(a, ph) do {                                                       \
    uint32_t _m = (a), _p = (ph), _d;                                               \
    asm volatile("{\n\t.reg .pred p;\n\t"                                           \
        "mbarrier.try_wait.parity.acquire.cta.shared::cta.b64 p, [%1], %2;\n\t"     \
        "selp.b32 %0, 1, 0, p;\n\t}" : "=r"(_d) : "r"(_m), "r"(_p) : "memory");     \
    if (!_d) {                                                                      \
        asm volatile("{\n\t.reg .pred P1;\n\tWL_%=:\n\t"                            \
            "mbarrier.try_wait.parity.acquire.cta.shared::cta.b64 P1, [%0], %1, 0x989680;\n\t" \
            "@P1 bra.uni WD_%=;\n\tbra.uni WL_%=;\n\tWD_%=:\n\t}"                   \
            :: "r"(_m), "r"(_p) : "memory");                                        \
    }                                                                               \
} while (0)
#define TC_ALLOC(sa, n)   asm volatile("tcgen05.alloc.cta_group::1.sync.aligned.shared::cta.b32 [%0], %1;" :: "r"(sa), "r"(n) : "memory")
#define TC_DEALLOC(t, n)  asm volatile("tcgen05.dealloc.cta_group::1.sync.aligned.b32 %0, %1;" :: "r"(t), "r"(n))
#define TC_RELINQ()       asm volatile("tcgen05.relinquish_alloc_permit.cta_group::1.sync.aligned;")
#define TC_COMMIT(mb)     asm volatile("tcgen05.commit.cta_group::1.mbarrier::arrive::one.shared::cluster.b64 [%0];" :: "r"(mb) : "memory")
#define TC_WAIT_LD()      asm volatile("tcgen05.wait::ld.sync.aligned;" ::: "memory")
#define TC_FENCE_BEFORE() asm volatile("tcgen05.fence::before_thread_sync;" ::: "memory")
#define TC_FENCE_AFTER()  asm volatile("tcgen05.fence::after_thread_sync;" ::: "memory")
#define FENCE_ASYNC()     asm volatile("fence.proxy.async.shared::cta;" ::: "memory")
#define BAR_PROD()        asm volatile("bar.sync 1, 128;" ::: "memory")
#define CP_ASYNC16(d, s)  asm volatile("cp.async.cg.shared.global [%0], [%1], 16;" :: "r"(d), "l"(s) : "memory")
#define CP_COMMIT()       asm volatile("cp.async.commit_group;" ::: "memory")
#define CP_WAIT0()        asm volatile("cp.async.wait_group 0;" ::: "memory")

__device__ __forceinline__ void mma_f16_ss(uint32_t d, uint64_t ad, uint64_t bd,
                                           uint32_t idesc, uint32_t en) {
    asm volatile(
        "{\n\t.reg .pred p;\n\tsetp.ne.u32 p, %5, 0;\n\t"
        "tcgen05.mma.cta_group::1.kind::f16 [%0], %1, %2, %3, {%4, %4, %4, %4}, p;\n\t}"
        :: "r"(d), "l"(ad), "l"(bd), "r"(idesc), "r"(0u), "r"(en) : "memory");
}
__device__ __forceinline__ uint64_t mk_desc(uint32_t addr) {
    return ((uint64_t)2 << 61) | ((uint64_t)1 << 46) | ((uint64_t)64 << 32)
         | ((uint64_t)1 << 16) | ((uint64_t)(addr >> 4) & 0x3FFF);
}
#define LDTM_X32(r, a)                                                              \
    asm volatile("tcgen05.ld.sync.aligned.32x32b.x32.b32 "                          \
        "{%0,%1,%2,%3,%4,%5,%6,%7,%8,%9,%10,%11,%12,%13,%14,%15,"                   \
        "%16,%17,%18,%19,%20,%21,%22,%23,%24,%25,%26,%27,%28,%29,%30,%31}, [%32];"  \
        : "=r"((r)[0]),"=r"((r)[1]),"=r"((r)[2]),"=r"((r)[3]),                       \
          "=r"((r)[4]),"=r"((r)[5]),"=r"((r)[6]),"=r"((r)[7]),                       \
          "=r"((r)[8]),"=r"((r)[9]),"=r"((r)[10]),"=r"((r)[11]),                     \
          "=r"((r)[12]),"=r"((r)[13]),"=r"((r)[14]),"=r"((r)[15]),                   \
          "=r"((r)[16]),"=r"((r)[17]),"=r"((r)[18]),"=r"((r)[19]),                   \
          "=r"((r)[20]),"=r"((r)[21]),"=r"((r)[22]),"=r"((r)[23]),                   \
          "=r"((r)[24]),"=r"((r)[25]),"=r"((r)[26]),"=r"((r)[27]),                   \
          "=r"((r)[28]),"=r"((r)[29]),"=r"((r)[30]),"=r"((r)[31]) : "r"(a))

// async chunk loader: pure 16B cp.async copies, no data registers.
// 128 producer threads; X tile 256 rows (2 batches x 128 t), W tile 128 rows; SW128.
template <int K>
__device__ __forceinline__ void load_chunk_async(uint32_t smbuf,
        const __nv_bfloat16* __restrict__ Xhi, const __nv_bfloat16* __restrict__ Xlo,
        const __nv_bfloat16* __restrict__ Whi, const __nv_bfloat16* __restrict__ Wlo,
        int h0, int bp, int t0, int kc, int ltid) {
    #pragma unroll
    for (int q = 0; q < 2; q++) {
        const int bmat = bp * 2 + q;
        const int r = q * 128 + ltid;
        const size_t rowelem = ((size_t)bmat * T_ + (t0 + ltid)) * K + kc;
        const char* shi = (const char*)(Xhi + rowelem);
        const char* slo = (const char*)(Xlo + rowelem);
        #pragma unroll
        for (int p = 0; p < 8; p++) {
            uint32_t off = r * 128 + p * 16;
            uint32_t sw = off ^ ((off >> 3) & 0x70);
            CP_ASYNC16(smbuf + OFF_XH + sw, shi + p * 16);
            CP_ASYNC16(smbuf + OFF_XL + sw, slo + p * 16);
        }
    }
    {
        const size_t rowelem = (size_t)(h0 + ltid) * K + kc;
        const char* shi = (const char*)(Whi + rowelem);
        const char* slo = (const char*)(Wlo + rowelem);
        #pragma unroll
        for (int p = 0; p < 8; p++) {
            uint32_t off = ltid * 128 + p * 16;
            uint32_t sw = off ^ ((off >> 3) & 0x70);
            CP_ASYNC16(smbuf + OFF_WH + sw, shi + p * 16);
            CP_ASYNC16(smbuf + OFF_WL + sw, slo + p * 16);
        }
    }
    CP_COMMIT();
    CP_WAIT0();
    BAR_PROD();
}
#endif  // USE_TC

// ---------------- fp32 -> planar bf16 hi/lo split ----------------
__global__ void split_kernel(const float* __restrict__ src,
                             __nv_bfloat16* __restrict__ hi,
                             __nv_bfloat16* __restrict__ lo, int n) {
    for (int i = blockIdx.x * blockDim.x + threadIdx.x; i < n; i += gridDim.x * blockDim.x) {
        float v = src[i];
        __nv_bfloat16 h = __float2bfloat16(v);
        hi[i] = h;
        lo[i] = __float2bfloat16(v - __bfloat162float(h));
    }
}

// ================ fused layer: GEMM (bf16x2) + in-register scan ================
// grid (H_/128, B_/2), block 256. D[128 h-lanes, 256 cols = 2 batches x 128 t].
// warps 0-3: scan consumer; warps 4-7: cp.async producer + MMA issue (warp 4 elect).
template <int K>
__global__ void __launch_bounds__(TPB, 1)
layer_tc(const __nv_bfloat16* __restrict__ Xhi, const __nv_bfloat16* __restrict__ Xlo,
         const __nv_bfloat16* __restrict__ Whi, const __nv_bfloat16* __restrict__ Wlo,
         const float* __restrict__ bl, const float* __restrict__ u, const float* __restrict__ bb,
         __nv_bfloat16* __restrict__ Hhi, __nv_bfloat16* __restrict__ Hlo) {
    extern __shared__ char smem[];
    const int tid = threadIdx.x;
    const int h0 = blockIdx.x * 128;
    const int bp = blockIdx.y;
#if USE_TC
    constexpr int C = K / KC;
    constexpr int NTILES = T_ / 128;
    const uint32_t smb = smem_to_u32(smem);
    const int wid = tid >> 5;

    if (tid == 0) {
        MBAR_INIT(smb + MB_BUFFREE0, 1); MBAR_INIT(smb + MB_BUFFREE0 + 8, 1);
        MBAR_INIT(smb + MB_TILERDY0, 1); MBAR_INIT(smb + MB_TILERDY0 + 8, 1);
        MBAR_INIT(smb + MB_SCAND0, 128); MBAR_INIT(smb + MB_SCAND0 + 8, 128);
    }
    if (wid == 0) { TC_ALLOC(smb, 512); TC_RELINQ(); }
    __syncthreads();
    uint32_t tmem;
    asm volatile("ld.shared.b32 %0, [%1];" : "=r"(tmem) : "r"(smb));

    if (wid >= 4) {
        // ---------------- producer ----------------
        const int ltid = tid - 128;
        int cnt[2] = {0, 0};
        for (int j = 0; j < NTILES; j++) {
            const int t0 = j * 128;
            for (int c = 0; c < C; c++) {
                const int b = (j * C + c) & 1;
                if (cnt[b]) MBAR_WAIT(smb + MB_BUFFREE0 + 8 * b, (cnt[b] - 1) & 1);
                const uint32_t smbuf = smb + SM_BUF0 + b * CHUNK_BYTES;
                load_chunk_async<K>(smbuf, Xhi, Xlo, Whi, Wlo, h0, bp, t0, c * KC, ltid);
                FENCE_ASYNC();
                if (wid == 4 && elect_one_pred()) {
                    if (c == 0 && j >= 2)
                        MBAR_WAIT(smb + MB_SCAND0 + 8 * (j & 1), ((j >> 1) - 1) & 1);
                    const uint64_t dWH = mk_desc(smbuf + OFF_WH), dWL = mk_desc(smbuf + OFF_WL);
                    const uint64_t dXH = mk_desc(smbuf + OFF_XH), dXL = mk_desc(smbuf + OFF_XL);
                    const uint32_t dacc = tmem + (j & 1) * 256;
                    #pragma unroll
                    for (int k = 0; k < 4; k++) {
                        const uint64_t o = (uint64_t)(k * 2);
                        mma_f16_ss(dacc, dWH + o, dXH + o, IDESC_128x256,
                                   (c == 0 && k == 0) ? 0u : 1u);
                        mma_f16_ss(dacc, dWH + o, dXL + o, IDESC_128x256, 1u);
                        mma_f16_ss(dacc, dWL + o, dXH + o, IDESC_128x256, 1u);
                    }
                    TC_COMMIT(smb + MB_BUFFREE0 + 8 * b);
                    if (c == C - 1) TC_COMMIT(smb + MB_TILERDY0 + 8 * (j & 1));
                }
                cnt[b]++;
            }
        }
    } else {
        // ---------------- consumer: per-channel scan ----------------
        float car[2] = {0.0f, 0.0f};
        const float uu = u[h0 + tid];
        const float bi = bl[h0 + tid] + bb[h0 + tid];
        for (int j = 0; j < NTILES; j++) {
            const int t0 = j * 128;
            MBAR_WAIT(smb + MB_TILERDY0 + 8 * (j & 1), (j >> 1) & 1);
            TC_FENCE_AFTER();
            const uint32_t dbase = tmem + (j & 1) * 256;
            #pragma unroll
            for (int cb = 0; cb < 8; cb++) {
                uint32_t d[32];
                LDTM_X32(d, dbase + cb * 32);
                TC_WAIT_LD();
                const int q = cb >> 2;
                const int tb = (cb & 3) * 32;
                const size_t base = ((size_t)(bp * 2 + q) * T_ + t0 + tb) * H_ + h0 + tid;
                float cr = car[q];
                #pragma unroll
                for (int i = 0; i < 32; i++) {
                    float p = __uint_as_float(d[i]) + bi;
                    cr = fmaxf(fmaf(uu, cr, p), 0.0f);
                    __nv_bfloat16 hh = __float2bfloat16(cr);
                    Hhi[base + (size_t)i * H_] = hh;
                    Hlo[base + (size_t)i * H_] = __float2bfloat16(cr - __bfloat162float(hh));
                }
                car[q] = cr;
            }
            TC_FENCE_BEFORE();
            MBAR_ARRIVE(smb + MB_SCAND0 + 8 * (j & 1));
        }
    }
    __syncthreads();
    if (tid == 0) {
        MBAR_INVAL(smb + MB_BUFFREE0); MBAR_INVAL(smb + MB_BUFFREE0 + 8);
        MBAR_INVAL(smb + MB_TILERDY0); MBAR_INVAL(smb + MB_TILERDY0 + 8);
        MBAR_INVAL(smb + MB_SCAND0);   MBAR_INVAL(smb + MB_SCAND0 + 8);
    }
    __syncthreads();
    if (wid == 0) TC_DEALLOC(tmem, 512);
#else
    // SIMT fallback
    float* xrow = (float*)smem;
    const int h = h0 + (tid < 128 ? tid : 0);
    float uu = 0.0f, bi = 0.0f;
    if (tid < 128) { uu = u[h]; bi = bl[h] + bb[h]; }
    const __nv_bfloat16* wh = Whi + (size_t)h * K;
    const __nv_bfloat16* wl = Wlo + (size_t)h * K;
    for (int q = 0; q < 2; q++) {
        const int bmat = bp * 2 + q;
        float hcar = 0.0f;
        for (int t = 0; t < T_; t++) {
            __syncthreads();
            size_t xr = ((size_t)bmat * T_ + t) * K;
            for (int i = tid; i < K; i += TPB)
                xrow[i] = __bfloat162float(Xhi[xr + i]) + __bfloat162float(Xlo[xr + i]);
            __syncthreads();
            if (tid < 128) {
                float acc = 0.0f;
                for (int k = 0; k < K; k++)
                    acc += (__bfloat162float(wh[k]) + __bfloat162float(wl[k])) * xrow[k];
                hcar = fmaxf(acc + bi + uu * hcar, 0.0f);
                size_t oi = ((size_t)bmat * T_ + t) * H_ + h0 + tid;
                __nv_bfloat16 hh = __float2bfloat16(hcar);
                Hhi[oi] = hh;
                Hlo[oi] = __float2bfloat16(hcar - __bfloat162float(hh));
            }
        }
    }
#endif
}

// ================ FC: out[b,t,o] = h2 . fcW[o,:] + fcb[o] ================
// grid (4 tgroups, B_/2), block 256.
__global__ void __launch_bounds__(TPB, 1)
fc_tc(const __nv_bfloat16* __restrict__ Xhi, const __nv_bfloat16* __restrict__ Xlo,
      const __nv_bfloat16* __restrict__ Whi, const __nv_bfloat16* __restrict__ Wlo,
      const float* __restrict__ bias, float* __restrict__ out) {
    extern __shared__ char smem[];
    const int tid = threadIdx.x;
    const int tg = blockIdx.x;
    const int bp = blockIdx.y;
#if USE_TC
    constexpr int C = H_ / KC;   // 8
    constexpr int NTILES = 4;
    const uint32_t smb = smem_to_u32(smem);
    const int wid = tid >> 5;

    if (tid == 0) {
        MBAR_INIT(smb + MB_BUFFREE0, 1); MBAR_INIT(smb + MB_BUFFREE0 + 8, 1);
        MBAR_INIT(smb + MB_TILERDY0, 1); MBAR_INIT(smb + MB_TILERDY0 + 8, 1);
        MBAR_INIT(smb + MB_SCAND0, 128); MBAR_INIT(smb + MB_SCAND0 + 8, 128);
    }
    if (wid == 0) { TC_ALLOC(smb, 512); TC_RELINQ(); }
    __syncthreads();
    uint32_t tmem;
    asm volatile("ld.shared.b32 %0, [%1];" : "=r"(tmem) : "r"(smb));

    if (wid >= 4) {
        const int ltid = tid - 128;
        int cnt[2] = {0, 0};
        for (int j = 0; j < NTILES; j++) {
            const int t0 = tg * 512 + j * 128;
            for (int c = 0; c < C; c++) {
                const int b = (j * C + c) & 1;
                if (cnt[b]) MBAR_WAIT(smb + MB_BUFFREE0 + 8 * b, (cnt[b] - 1) & 1);
                const uint32_t smbuf = smb + SM_BUF0 + b * CHUNK_BYTES;
                load_chunk_async<H_>(smbuf, Xhi, Xlo, Whi, Wlo, 0, bp, t0, c * KC, ltid);
                FENCE_ASYNC();
                if (wid == 4 && elect_one_pred()) {
                    if (c == 0 && j >= 2)
                        MBAR_WAIT(smb + MB_SCAND0 + 8 * (j & 1), ((j >> 1) - 1) & 1);
                    const uint64_t dWH = mk_desc(smbuf + OFF_WH), dWL = mk_desc(smbuf + OFF_WL);
                    const uint64_t dXH = mk_desc(smbuf + OFF_XH), dXL = mk_desc(smbuf + OFF_XL);
                    const uint32_t dacc = tmem + (j & 1) * 256;
                    #pragma unroll
                    for (int k = 0; k < 4; k++) {
                        const uint64_t o = (uint64_t)(k * 2);
                        mma_f16_ss(dacc, dWH + o, dXH + o, IDESC_128x256,
                                   (c == 0 && k == 0) ? 0u : 1u);
                        mma_f16_ss(dacc, dWH + o, dXL + o, IDESC_128x256, 1u);
                        mma_f16_ss(dacc, dWL + o, dXH + o, IDESC_128x256, 1u);
                    }
                    TC_COMMIT(smb + MB_BUFFREE0 + 8 * b);
                    if (c == C - 1) TC_COMMIT(smb + MB_TILERDY0 + 8 * (j & 1));
                }
                cnt[b]++;
            }
        }
    } else {
        const float bo = bias[tid];
        for (int j = 0; j < NTILES; j++) {
            const int t0 = tg * 512 + j * 128;
            MBAR_WAIT(smb + MB_TILERDY0 + 8 * (j & 1), (j >> 1) & 1);
            TC_FENCE_AFTER();
            const uint32_t dbase = tmem + (j & 1) * 256;
            #pragma unroll
            for (int cb = 0; cb < 8; cb++) {
                uint32_t d[32];
                LDTM_X32(d, dbase + cb * 32);
                TC_WAIT_LD();
                const int q = cb >> 2;
                const int tb = (cb & 3) * 32;
                float* op = out + ((size_t)(bp * 2 + q) * T_ + t0 + tb) * DOUT + tid;
                #pragma unroll
                for (int i = 0; i < 32; i++)
                    op[(size_t)i * DOUT] = __uint_as_float(d[i]) + bo;
            }
            TC_FENCE_BEFORE();
            MBAR_ARRIVE(smb + MB_SCAND0 + 8 * (j & 1));
        }
    }
    __syncthreads();
    if (tid == 0) {
        MBAR_INVAL(smb + MB_BUFFREE0); MBAR_INVAL(smb + MB_BUFFREE0 + 8);
        MBAR_INVAL(smb + MB_TILERDY0); MBAR_INVAL(smb + MB_TILERDY0 + 8);
        MBAR_INVAL(smb + MB_SCAND0);   MBAR_INVAL(smb + MB_SCAND0 + 8);
    }
    __syncthreads();
    if (wid == 0) TC_DEALLOC(tmem, 512);
#else
    // SIMT fallback
    float* xrow = (float*)smem;
    const __nv_bfloat16* wh = Whi + (size_t)(tid < 128 ? tid : 0) * H_;
    const __nv_bfloat16* wl = Wlo + (size_t)(tid < 128 ? tid : 0) * H_;
    float bo = (tid < 128) ? bias[tid] : 0.0f;
    for (int q = 0; q < 2; q++) {
        const int bmat = bp * 2 + q;
        for (int tt = 0; tt < 512; tt++) {
            const int t = tg * 512 + tt;
            __syncthreads();
            size_t xr = ((size_t)bmat * T_ + t) * H_;
            for (int i = tid; i < H_; i += TPB)
                xrow[i] = __bfloat162float(Xhi[xr + i]) + __bfloat162float(Xlo[xr + i]);
            __syncthreads();
            if (tid < 128) {
                float acc = 0.0f;
                for (int k = 0; k < H_; k++)
                    acc += (__bfloat162float(wh[k]) + __bfloat162float(wl[k])) * xrow[k];
                out[((size_t)bmat * T_ + t) * DOUT + tid] = acc + bo;
            }
        }
    }
#endif
}

extern "C" void kernel_launch(void* const* d_in, const int* in_sizes, int n_in,
                              void* d_out, int out_size) {
    const float* x   = (const float*)d_in[0];
    const float* W0  = (const float*)d_in[1];
    const float* bl0 = (const float*)d_in[2];
    const float* u0  = (const float*)d_in[3];
    const float* bb0 = (const float*)d_in[4];
    const float* W1  = (const float*)d_in[5];
    const float* bl1 = (const float*)d_in[6];
    const float* u1  = (const float*)d_in[7];
    const float* bb1 = (const float*)d_in[8];
    const float* fcW = (const float*)d_in[9];
    const float* fcb = (const float*)d_in[10];
    float* out = (float*)d_out;

    __nv_bfloat16 *xhi, *xlo, *h1hi, *h1lo, *h2hi, *h2lo;
    __nv_bfloat16 *w0hi, *w0lo, *w1hi, *w1lo, *fwhi, *fwlo;
    cudaGetSymbolAddress((void**)&xhi,  g_xhi);
    cudaGetSymbolAddress((void**)&xlo,  g_xlo);
    cudaGetSymbolAddress((void**)&h1hi, g_h1hi);
    cudaGetSymbolAddress((void**)&h1lo, g_h1lo);
    cudaGetSymbolAddress((void**)&h2hi, g_h2hi);
    cudaGetSymbolAddress((void**)&h2lo, g_h2lo);
    cudaGetSymbolAddress((void**)&w0hi, g_W0hi);
    cudaGetSymbolAddress((void**)&w0lo, g_W0lo);
    cudaGetSymbolAddress((void**)&w1hi, g_W1hi);
    cudaGetSymbolAddress((void**)&w1lo, g_W1lo);
    cudaGetSymbolAddress((void**)&fwhi, g_fWhi);
    cudaGetSymbolAddress((void**)&fwlo, g_fWlo);

    cudaFuncSetAttribute(layer_tc<DIN>, cudaFuncAttributeMaxDynamicSharedMemorySize, SM_TOTAL);
    cudaFuncSetAttribute(layer_tc<H_>,  cudaFuncAttributeMaxDynamicSharedMemorySize, SM_TOTAL);
    cudaFuncSetAttribute(fc_tc,         cudaFuncAttributeMaxDynamicSharedMemorySize, SM_TOTAL);

    split_kernel<<<1024, 256>>>(x,   xhi,  xlo,  B_ * T_ * DIN);
    split_kernel<<<64,   256>>>(W0,  w0hi, w0lo, H_ * DIN);
    split_kernel<<<256,  256>>>(W1,  w1hi, w1lo, H_ * H_);
    split_kernel<<<64,   256>>>(fcW, fwhi, fwlo, DOUT * H_);

    dim3 lgrid(H_ / 128, B_ / 2);     // (4, 32)
    layer_tc<DIN><<<lgrid, TPB, SM_TOTAL>>>(xhi, xlo, w0hi, w0lo, bl0, u0, bb0, h1hi, h1lo);
    layer_tc<H_> <<<lgrid, TPB, SM_TOTAL>>>(h1hi, h1lo, w1hi, w1lo, bl1, u1, bb1, h2hi, h2lo);
    dim3 fgrid(4, B_ / 2);            // (4, 32)
    fc_tc<<<fgrid, TPB, SM_TOTAL>>>(h2hi, h2lo, fwhi, fwlo, fcb, out);
}